// round 14
// baseline (speedup 1.0000x reference)
#include <cuda_runtime.h>
#include <cuda_fp16.h>
#include <math.h>
#include <float.h>
#include <stdint.h>

// Problem constants (fixed shapes from reference setup_inputs)
#define NIMG 2
#define MBOX 1000
#define NBOX (NIMG*MBOX)
#define CCH  256
#define RR   7
#define FCIN (CCH*RR*RR)      // 12544
#define FCD  1024
#define SORT_N 1024
#define NWORDS 16             // ceil(1000/64)
#define SCORE_THRESH 0.05f
#define NMS_THRESH 0.5f
#define TOPK 100
#define SCALE_CLAMP 4.135166556742356f  // log(1000/16)

// ---------------- scratch (device globals; no allocations allowed) ----------
__device__ float g_Y1[NBOX * FCD];
__device__ float g_Y2[NBOX * FCD];
__device__ float g_scores[NBOX];
__device__ float g_pboxes[NBOX * 4];  // clipped predicted boxes
__device__ unsigned long long g_sup[NIMG * MBOX * NWORDS];
// per-box gather descriptors (fused pooling)
__device__ const float* g_pbase[NBOX];
__device__ int g_pHW[NBOX];
__device__ int g_offt[NBOX * 49];

// ---------------- per-box descriptor build (replaces pool materialization) --
__global__ void desc_kernel(const float* __restrict__ p2, const float* __restrict__ p3,
                            const float* __restrict__ p4, const float* __restrict__ p5,
                            const float* __restrict__ props)
{
    int box = blockIdx.x * blockDim.x + threadIdx.x;
    if (box >= NBOX) return;
    int img = box / MBOX;

    const float* fmaps[4] = {p2, p3, p4, p5};
    const int   Hs[4] = {200, 100, 50, 25};
    const int   Ws[4] = {304, 152, 76, 38};
    const float sc4[4] = {0.25f, 0.125f, 0.0625f, 0.03125f};

    const float* pr = props + (size_t)box * 4;
    float x1o = pr[0], y1o = pr[1], x2o = pr[2], y2o = pr[3];

    float w = __fsub_rn(x2o, x1o);
    float h = __fsub_rn(y2o, y1o);
    float s = sqrtf(fmaxf(__fmul_rn(w, h), 1e-6f));
    float lv = floorf(__fadd_rn(4.0f, log2f(__fadd_rn(__fdiv_rn(s, 224.0f), 1e-8f))));
    lv = fminf(fmaxf(lv, 2.0f), 5.0f);
    int lvl = (int)lv - 2;      // 0..3

    float sc = sc4[lvl];        // powers of two: multiply is exact
    float x1 = __fmul_rn(x1o, sc), y1 = __fmul_rn(y1o, sc);
    float x2 = __fmul_rn(x2o, sc), y2 = __fmul_rn(y2o, sc);
    float bw = __fdiv_rn(fmaxf(__fsub_rn(x2, x1), 1.0f), 7.0f);
    float bh = __fdiv_rn(fmaxf(__fsub_rn(y2, y1), 1.0f), 7.0f);
    int Wl = Ws[lvl], Hl = Hs[lvl];
    int six[RR], siy[RR];
    for (int j = 0; j < RR; j++) {
        float cs = (float)j + 0.5f;
        float gx = __fadd_rn(x1, __fmul_rn(cs, bw));
        float gy = __fadd_rn(y1, __fmul_rn(cs, bh));
        six[j] = min(max((int)gx, 0), Wl - 1);
        siy[j] = min(max((int)gy, 0), Hl - 1);
    }
    g_pbase[box] = fmaps[lvl] + (size_t)img * CCH * Hl * Wl;
    g_pHW[box] = Hl * Wl;
    for (int p = 0; p < 49; p++)
        g_offt[box * 49 + p] = siy[p / 7] * Wl + six[p % 7];
}

// ---------------- fp16x3 scaled-split tensor GEMM, chunk-compensated --------
// C = relu(A @ B + bias).  GATHER=true: A rows are pooled features gathered
// on the fly via g_pbase/g_pHW/g_offt (k -> c=k/49, p=k%49, base[c*HW+off[p]]);
// values bit-identical to the materialized pool. GATHER=false: A from gmem.
// Split: hi = fp16(x); lo' = fp16((x - hi) * 2048).  Per k16-step 3 MMAs:
// chh += hiA*hiB; cmix += hiA*lo'B + lo'A*hiB.  Fold every 4 tiles (64 k):
// y = fma(cmix, 2^-11, chh); fast2sum into master s (R8-class numerics).
__device__ __forceinline__ void mma_f16(float* c, const uint32_t* a,
                                        uint32_t b0, uint32_t b1) {
    asm volatile(
        "mma.sync.aligned.m16n8k16.row.col.f32.f16.f16.f32 "
        "{%0,%1,%2,%3},{%4,%5,%6,%7},{%8,%9},{%0,%1,%2,%3};\n"
        : "+f"(c[0]), "+f"(c[1]), "+f"(c[2]), "+f"(c[3])
        : "r"(a[0]), "r"(a[1]), "r"(a[2]), "r"(a[3]), "r"(b0), "r"(b1));
}
__device__ __forceinline__ uint32_t split_pair(float x0, float x1, uint32_t& mix) {
    __half h0 = __float2half_rn(x0), h1 = __float2half_rn(x1);
    float r0 = __fmul_rn(__fsub_rn(x0, __half2float(h0)), 2048.0f);
    float r1 = __fmul_rn(__fsub_rn(x1, __half2float(h1)), 2048.0f);
    __half2 m2 = __halves2half2(__float2half_rn(r0), __float2half_rn(r1));
    mix = *(uint32_t*)&m2;
    __half2 h2 = __halves2half2(h0, h1);
    return *(uint32_t*)&h2;
}

template<bool RELU, bool GATHER>
__global__ void __launch_bounds__(256) tcgemm_kernel(
    const float* __restrict__ A, const float* __restrict__ B,
    const float* __restrict__ bias, float* __restrict__ Cmat,
    int Mrows, int Kdim, int Ndim)
{
    const int BM = 128, BN = 64, BK = 16;
    const int PA = 132;   // A half2-word pitch (128 rows + 4 pad)
    const int PB = 68;    // B half2-word pitch (64 cols + 4 pad)
    __shared__ uint32_t Ah[2][8][PA], Am[2][8][PA];
    __shared__ uint32_t Bh[2][8][PB], Bm[2][8][PB];

    int tid = threadIdx.x;
    int lane = tid & 31, wid = tid >> 5;
    int g = lane >> 2, tig = lane & 3;
    int warp_m = (wid & 3) * 32;     // 4 warps cover 128 m
    int warp_n = (wid >> 2) * 32;    // 2 warps cover 64 n
    int bm = blockIdx.y * BM, bn = blockIdx.x * BN;

    float s[2][4][4], chh[2][4][4], cmix[2][4][4];
    #pragma unroll
    for (int mt = 0; mt < 2; mt++)
        #pragma unroll
        for (int nt = 0; nt < 4; nt++)
            #pragma unroll
            for (int q = 0; q < 4; q++) {
                s[mt][nt][q] = 0.f; chh[mt][nt][q] = 0.f; cmix[mt][nt][q] = 0.f;
            }

    // fill mapping: A 128m x 16k, 8 elems/thread; B 16k x 64n, two float2/thread
    int am = tid >> 1, ak = (tid & 1) * 8;       // ak = 0 or 8
    int bk2 = tid >> 5, bn2 = (tid & 31) * 2;    // k2 row 0..7, n pair
    int gr = bm + am;
    bool a_ok = (gr < Mrows);
    const float* Aptr = A + (size_t)(a_ok ? gr : 0) * Kdim + ak;
    const float* Bptr0 = B + (size_t)(2 * bk2 + 0) * Ndim + bn + bn2;
    const float* Bptr1 = B + (size_t)(2 * bk2 + 1) * Ndim + bn + bn2;

    // gather descriptor (per-thread box fixed for the whole kernel)
    const float* gbase = nullptr;
    int gHW = 0;
    const int* gofft = nullptr;
    if (GATHER && a_ok) {
        gbase = g_pbase[gr];
        gHW = g_pHW[gr];
        gofft = g_offt + gr * 49;
    }

    float va[8];
    float2 bv0, bv1;
    // fetch tile 0
    #pragma unroll
    for (int j = 0; j < 8; j++) va[j] = 0.f;
    if (a_ok) {
        if (GATHER) {
            #pragma unroll
            for (int j = 0; j < 8; j++) {
                int k = ak + j;
                int c = k / 49, p = k - c * 49;
                va[j] = __ldg(gbase + (size_t)c * gHW + gofft[p]);
            }
        } else {
            float4 t0 = *(const float4*)(Aptr);
            float4 t1 = *(const float4*)(Aptr + 4);
            va[0]=t0.x; va[1]=t0.y; va[2]=t0.z; va[3]=t0.w;
            va[4]=t1.x; va[5]=t1.y; va[6]=t1.z; va[7]=t1.w;
        }
    }
    bv0 = *(const float2*)(Bptr0);
    bv1 = *(const float2*)(Bptr1);

    // store tile 0
    {
        uint32_t m0, m1, m2w, m3;
        Ah[0][ak/2 + 0][am] = split_pair(va[0], va[1], m0); Am[0][ak/2 + 0][am] = m0;
        Ah[0][ak/2 + 1][am] = split_pair(va[2], va[3], m1); Am[0][ak/2 + 1][am] = m1;
        Ah[0][ak/2 + 2][am] = split_pair(va[4], va[5], m2w); Am[0][ak/2 + 2][am] = m2w;
        Ah[0][ak/2 + 3][am] = split_pair(va[6], va[7], m3); Am[0][ak/2 + 3][am] = m3;
        uint32_t mb0, mb1;
        Bh[0][bk2][bn2 + 0] = split_pair(bv0.x, bv1.x, mb0); Bm[0][bk2][bn2 + 0] = mb0;
        Bh[0][bk2][bn2 + 1] = split_pair(bv0.y, bv1.y, mb1); Bm[0][bk2][bn2 + 1] = mb1;
    }
    __syncthreads();

    int buf = 0, tile = 0;
    for (int k0 = BK; k0 <= Kdim; k0 += BK) {
        // prefetch next tile into registers
        if (k0 < Kdim) {
            if (a_ok) {
                if (GATHER) {
                    #pragma unroll
                    for (int j = 0; j < 8; j++) {
                        int k = k0 + ak + j;
                        int c = k / 49, p = k - c * 49;
                        va[j] = __ldg(gbase + (size_t)c * gHW + gofft[p]);
                    }
                } else {
                    float4 t0 = *(const float4*)(Aptr + k0);
                    float4 t1 = *(const float4*)(Aptr + k0 + 4);
                    va[0]=t0.x; va[1]=t0.y; va[2]=t0.z; va[3]=t0.w;
                    va[4]=t1.x; va[5]=t1.y; va[6]=t1.z; va[7]=t1.w;
                }
            }
            bv0 = *(const float2*)(Bptr0 + (size_t)k0 * Ndim);
            bv1 = *(const float2*)(Bptr1 + (size_t)k0 * Ndim);
        }

        // ---- A fragments up front; B per nt (proven schedule) ----
        uint32_t aH[2][4], aM[2][4];
        #pragma unroll
        for (int mt = 0; mt < 2; mt++) {
            int r0 = warp_m + mt * 16 + g;
            aH[mt][0] = Ah[buf][tig    ][r0    ];
            aH[mt][1] = Ah[buf][tig    ][r0 + 8];
            aH[mt][2] = Ah[buf][tig + 4][r0    ];
            aH[mt][3] = Ah[buf][tig + 4][r0 + 8];
            aM[mt][0] = Am[buf][tig    ][r0    ];
            aM[mt][1] = Am[buf][tig    ][r0 + 8];
            aM[mt][2] = Am[buf][tig + 4][r0    ];
            aM[mt][3] = Am[buf][tig + 4][r0 + 8];
        }
        #pragma unroll
        for (int nt = 0; nt < 4; nt++) {
            int nn = warp_n + nt * 8 + g;
            uint32_t b0h = Bh[buf][tig    ][nn];
            uint32_t b1h = Bh[buf][tig + 4][nn];
            uint32_t b0m = Bm[buf][tig    ][nn];
            uint32_t b1m = Bm[buf][tig + 4][nn];
            #pragma unroll
            for (int mt = 0; mt < 2; mt++) {
                mma_f16(chh[mt][nt],  aH[mt], b0h, b1h);   // hi*hi
                mma_f16(cmix[mt][nt], aH[mt], b0m, b1m);   // hi*lo'
                mma_f16(cmix[mt][nt], aM[mt], b0h, b1h);   // lo'*hi
            }
        }

        // ---- fold every 4 tiles (64 k): combine scales + fast2sum ----
        tile++;
        if ((tile & 3) == 0) {
            #pragma unroll
            for (int mt = 0; mt < 2; mt++)
                #pragma unroll
                for (int nt = 0; nt < 4; nt++)
                    #pragma unroll
                    for (int q = 0; q < 4; q++) {
                        float y = __fmaf_rn(cmix[mt][nt][q], 4.8828125e-4f, chh[mt][nt][q]);
                        float t = __fadd_rn(s[mt][nt][q], y);
                        chh[mt][nt][q] = __fadd_rn(__fsub_rn(s[mt][nt][q], t), y);
                        cmix[mt][nt][q] = 0.f;
                        s[mt][nt][q] = t;
                    }
        }

        // ---- store prefetched tile into other buffer ----
        if (k0 < Kdim) {
            int nb = buf ^ 1;
            uint32_t m0, m1, m2w, m3;
            Ah[nb][ak/2 + 0][am] = split_pair(va[0], va[1], m0); Am[nb][ak/2 + 0][am] = m0;
            Ah[nb][ak/2 + 1][am] = split_pair(va[2], va[3], m1); Am[nb][ak/2 + 1][am] = m1;
            Ah[nb][ak/2 + 2][am] = split_pair(va[4], va[5], m2w); Am[nb][ak/2 + 2][am] = m2w;
            Ah[nb][ak/2 + 3][am] = split_pair(va[6], va[7], m3); Am[nb][ak/2 + 3][am] = m3;
            uint32_t mb0, mb1;
            Bh[nb][bk2][bn2 + 0] = split_pair(bv0.x, bv1.x, mb0); Bm[nb][bk2][bn2 + 0] = mb0;
            Bh[nb][bk2][bn2 + 1] = split_pair(bv0.y, bv1.y, mb1); Bm[nb][bk2][bn2 + 1] = mb1;
            __syncthreads();
            buf = nb;
        }
    }

    // ---- epilogue: rows g / g+8, cols 2*tig, 2*tig+1 (chh holds final comp) --
    #pragma unroll
    for (int mt = 0; mt < 2; mt++) {
        int r0 = bm + warp_m + mt * 16 + g;
        #pragma unroll
        for (int nt = 0; nt < 4; nt++) {
            int col = bn + warp_n + nt * 8 + tig * 2;
            if (r0 < Mrows) {
                float v0 = __fadd_rn(__fadd_rn(s[mt][nt][0], chh[mt][nt][0]), bias[col]);
                float v1 = __fadd_rn(__fadd_rn(s[mt][nt][1], chh[mt][nt][1]), bias[col + 1]);
                if (RELU) { v0 = fmaxf(v0, 0.f); v1 = fmaxf(v1, 0.f); }
                *(float2*)(Cmat + (size_t)r0 * Ndim + col) = make_float2(v0, v1);
            }
            if (r0 + 8 < Mrows) {
                float v2 = __fadd_rn(__fadd_rn(s[mt][nt][2], chh[mt][nt][2]), bias[col]);
                float v3 = __fadd_rn(__fadd_rn(s[mt][nt][3], chh[mt][nt][3]), bias[col + 1]);
                if (RELU) { v2 = fmaxf(v2, 0.f); v3 = fmaxf(v3, 0.f); }
                *(float2*)(Cmat + (size_t)(r0 + 8) * Ndim + col) = make_float2(v2, v3);
            }
        }
    }
}

// ---------------- heads: cls/box projections + softmax + deltas + clip ------
__global__ void heads_kernel(const float* __restrict__ Y2,
                             const float* __restrict__ Wc, const float* __restrict__ bc,
                             const float* __restrict__ Wb, const float* __restrict__ bb,
                             const float* __restrict__ props,
                             const int* __restrict__ isz,
                             float* __restrict__ scores, float* __restrict__ pboxes)
{
    int box = blockIdx.x;
    const float* x = Y2 + (size_t)box * FCD;

    double a0 = 0., a1 = 0., a2 = 0., a3 = 0., a4 = 0., a5 = 0.;
    for (int k = threadIdx.x; k < FCD; k += blockDim.x) {
        double xv = (double)x[k];
        a0 += xv * (double)Wc[k * 2 + 0];
        a1 += xv * (double)Wc[k * 2 + 1];
        a2 += xv * (double)Wb[k * 4 + 0];
        a3 += xv * (double)Wb[k * 4 + 1];
        a4 += xv * (double)Wb[k * 4 + 2];
        a5 += xv * (double)Wb[k * 4 + 3];
    }
    __shared__ double red[6][128];
    red[0][threadIdx.x] = a0; red[1][threadIdx.x] = a1; red[2][threadIdx.x] = a2;
    red[3][threadIdx.x] = a3; red[4][threadIdx.x] = a4; red[5][threadIdx.x] = a5;
    __syncthreads();
    for (int s = 64; s > 0; s >>= 1) {
        if (threadIdx.x < s)
            #pragma unroll
            for (int j = 0; j < 6; j++)
                red[j][threadIdx.x] += red[j][threadIdx.x + s];
        __syncthreads();
    }
    if (threadIdx.x == 0) {
        float l0 = (float)(red[0][0] + (double)bc[0]);
        float l1 = (float)(red[1][0] + (double)bc[1]);
        float m = fmaxf(l0, l1);
        float e0 = expf(__fsub_rn(l0, m)), e1 = expf(__fsub_rn(l1, m));
        scores[box] = __fdiv_rn(e1, __fadd_rn(e0, e1));

        float dx = (float)(red[2][0] + (double)bb[0]);
        float dy = (float)(red[3][0] + (double)bb[1]);
        float dw = fminf((float)(red[4][0] + (double)bb[2]), SCALE_CLAMP);
        float dh = fminf((float)(red[5][0] + (double)bb[3]), SCALE_CLAMP);

        const float* pr = props + (size_t)box * 4;
        float w = __fsub_rn(pr[2], pr[0]), h = __fsub_rn(pr[3], pr[1]);
        float cx = __fadd_rn(pr[0], __fmul_rn(0.5f, w));
        float cy = __fadd_rn(pr[1], __fmul_rn(0.5f, h));
        float pcx = __fadd_rn(__fmul_rn(dx, w), cx);
        float pcy = __fadd_rn(__fmul_rn(dy, h), cy);
        float pw = __fmul_rn(expf(dw), w);
        float ph = __fmul_rn(expf(dh), h);

        int img = box / MBOX;
        float Hh = (float)isz[img * 2 + 0];
        float Ww = (float)isz[img * 2 + 1];
        float bx1 = fminf(fmaxf(__fsub_rn(pcx, __fmul_rn(0.5f, pw)), 0.f), Ww);
        float by1 = fminf(fmaxf(__fsub_rn(pcy, __fmul_rn(0.5f, ph)), 0.f), Hh);
        float bx2 = fminf(fmaxf(__fadd_rn(pcx, __fmul_rn(0.5f, pw)), 0.f), Ww);
        float by2 = fminf(fmaxf(__fadd_rn(pcy, __fmul_rn(0.5f, ph)), 0.f), Hh);
        pboxes[box * 4 + 0] = bx1;
        pboxes[box * 4 + 1] = by1;
        pboxes[box * 4 + 2] = bx2;
        pboxes[box * 4 + 3] = by2;
    }
}

// ---------------- per-image stable sort + NMS + topk + write outputs --------
__global__ void __launch_bounds__(512) sortnms_kernel(
    const float* __restrict__ scores, const float* __restrict__ pboxes,
    float* __restrict__ out)
{
    int img = blockIdx.x;
    int tid = threadIdx.x;

    __shared__ float key[SORT_N];
    __shared__ int   idx[SORT_N];
    __shared__ float4 sb[MBOX];
    __shared__ float  sarea[MBOX];
    __shared__ unsigned long long keepw[NWORDS];

    for (int i = tid; i < SORT_N; i += 512) {
        if (i < MBOX) { key[i] = scores[img * MBOX + i]; idx[i] = i; }
        else          { key[i] = -FLT_MAX;               idx[i] = i; }
    }
    __syncthreads();

    for (int k = 2; k <= SORT_N; k <<= 1) {
        for (int j = k >> 1; j > 0; j >>= 1) {
            for (int i = tid; i < SORT_N; i += 512) {
                int ixj = i ^ j;
                if (ixj > i) {
                    float ka = key[i], kb = key[ixj];
                    int ia = idx[i], ib = idx[ixj];
                    bool a_before_b = (ka > kb) || (ka == kb && ia < ib);
                    bool up = ((i & k) == 0);
                    bool sw = up ? !a_before_b : a_before_b;
                    if (sw) { key[i] = kb; key[ixj] = ka; idx[i] = ib; idx[ixj] = ia; }
                }
            }
            __syncthreads();
        }
    }

    for (int i = tid; i < MBOX; i += 512) {
        const float* p = pboxes + (size_t)(img * MBOX + idx[i]) * 4;
        float4 b = make_float4(p[0], p[1], p[2], p[3]);
        sb[i] = b;
        sarea[i] = (b.z - b.x) * (b.w - b.y);
    }
    __syncthreads();

    unsigned long long* sup = g_sup + (size_t)img * MBOX * NWORDS;
    for (int t = tid; t < MBOX * NWORDS; t += 512) {
        int i = t / NWORDS, w = t % NWORDS;
        float4 a = sb[i];
        float aa = sarea[i];
        unsigned long long m = 0ull;
        int j0 = w * 64;
        int jend = min(j0 + 64, MBOX);
        for (int j = max(j0, i + 1); j < jend; j++) {
            float4 b = sb[j];
            float lx = fmaxf(a.x, b.x), ly = fmaxf(a.y, b.y);
            float rx = fminf(a.z, b.z), ry = fminf(a.w, b.w);
            float iw = fmaxf(rx - lx, 0.f), ih = fmaxf(ry - ly, 0.f);
            float inter = iw * ih;
            float iou = inter / fmaxf(aa + sarea[j] - inter, 1e-9f);
            if (iou > NMS_THRESH) m |= 1ull << (j - j0);
        }
        sup[t] = m;
    }
    if (tid < NWORDS) {
        unsigned long long m = 0ull;
        for (int jj = 0; jj < 64; jj++) {
            int j = tid * 64 + jj;
            if (j < MBOX && key[j] > SCORE_THRESH) m |= 1ull << jj;
        }
        keepw[tid] = m;
    }
    __syncthreads();

    if (tid < 32) {
        volatile unsigned long long* kw = keepw;
        for (int i = 0; i < MBOX; i++) {
            unsigned long long kwi = kw[i >> 6];
            __syncwarp();
            if ((kwi >> (i & 63)) & 1ull) {
                if (tid < NWORDS)
                    kw[tid] = kw[tid] & ~sup[(size_t)i * NWORDS + tid];
            }
            __syncwarp();
        }
        if (tid == 0) {
            int cnt = 0;
            for (int i = 0; i < MBOX; i++) {
                int w = i >> 6, b = i & 63;
                if ((kw[w] >> b) & 1ull) {
                    cnt++;
                    if (cnt > TOPK) kw[w] = kw[w] & ~(1ull << b);
                }
            }
        }
    }
    __syncthreads();

    float* oB = out;
    float* oS = out + (size_t)NIMG * MBOX * 4;
    float* oK = oS + (size_t)NIMG * MBOX;
    float* oO = oK + (size_t)NIMG * MBOX;
    for (int i = tid; i < MBOX; i += 512) {
        float4 b = sb[i];
        size_t o = (size_t)(img * MBOX + i);
        oB[o * 4 + 0] = b.x;
        oB[o * 4 + 1] = b.y;
        oB[o * 4 + 2] = b.z;
        oB[o * 4 + 3] = b.w;
        oS[o] = key[i];
        int w = i >> 6, bb2 = i & 63;
        oK[o] = ((keepw[w] >> bb2) & 1ull) ? 1.0f : 0.0f;
        oO[o] = (float)idx[i];
    }
}

// ---------------- launcher ---------------------------------------------------
extern "C" void kernel_launch(void* const* d_in, const int* in_sizes, int n_in,
                              void* d_out, int out_size)
{
    const float* p2    = (const float*)d_in[0];
    const float* p3    = (const float*)d_in[1];
    const float* p4    = (const float*)d_in[2];
    const float* p5    = (const float*)d_in[3];
    const float* props = (const float*)d_in[4];
    const int*   isz   = (const int*)  d_in[5];
    const float* W1    = (const float*)d_in[6];
    const float* b1    = (const float*)d_in[7];
    const float* W2    = (const float*)d_in[8];
    const float* b2    = (const float*)d_in[9];
    const float* Wc    = (const float*)d_in[10];
    const float* bc    = (const float*)d_in[11];
    const float* Wb    = (const float*)d_in[12];
    const float* bb    = (const float*)d_in[13];
    float* out = (float*)d_out;

    void *pY1, *pY2, *pSc, *pPb;
    cudaGetSymbolAddress(&pY1, g_Y1);
    cudaGetSymbolAddress(&pY2, g_Y2);
    cudaGetSymbolAddress(&pSc, g_scores);
    cudaGetSymbolAddress(&pPb, g_pboxes);
    float* Y1 = (float*)pY1;
    float* Y2 = (float*)pY2;
    float* Sc = (float*)pSc;
    float* Pb = (float*)pPb;

    desc_kernel<<<(NBOX + 255) / 256, 256>>>(p2, p3, p4, p5, props);

    dim3 g1(FCD / 64, (NBOX + 127) / 128);   // 16 x 16
    // GEMM1: A gathered from feature maps on the fly (fused pooling)
    tcgemm_kernel<true, true><<<g1, 256>>>(nullptr, W1, b1, Y1, NBOX, FCIN, FCD);
    tcgemm_kernel<true, false><<<g1, 256>>>(Y1, W2, b2, Y2, NBOX, FCD, FCD);

    heads_kernel<<<NBOX, 128>>>(Y2, Wc, bc, Wb, bb, props, isz, Sc, Pb);

    sortnms_kernel<<<NIMG, 512>>>(Sc, Pb, out);
}

// round 15
// speedup vs baseline: 1.2411x; 1.2411x over previous
#include <cuda_runtime.h>
#include <cuda_fp16.h>
#include <math.h>
#include <float.h>
#include <stdint.h>

// Problem constants (fixed shapes from reference setup_inputs)
#define NIMG 2
#define MBOX 1000
#define NBOX (NIMG*MBOX)
#define CCH  256
#define RR   7
#define FCIN (CCH*RR*RR)      // 12544
#define FCD  1024
#define SORT_N 1024
#define NWORDS 16             // ceil(1000/64)
#define SCORE_THRESH 0.05f
#define NMS_THRESH 0.5f
#define TOPK 100
#define SCALE_CLAMP 4.135166556742356f  // log(1000/16)

// ---------------- scratch (device globals; no allocations allowed) ----------
__device__ float g_X [NBOX * FCIN];   // pooled features, row-major (2000 x 12544)
__device__ float g_Y1[NBOX * FCD];
__device__ float g_Y2[NBOX * FCD];
__device__ float g_scores[NBOX];
__device__ float g_pboxes[NBOX * 4];  // clipped predicted boxes
__device__ unsigned long long g_sup[NIMG * MBOX * NWORDS];

// ---------------- pooling (ROIAlign-nearest per reference) ------------------
// One block per box. Offsets precomputed in smem; 4 elements per thread-step
// (one div per group, incremental p), gathers via __ldg, STG.128 writes.
__global__ void pool_kernel(const float* __restrict__ p2, const float* __restrict__ p3,
                            const float* __restrict__ p4, const float* __restrict__ p5,
                            const float* __restrict__ props)
{
    int box = blockIdx.x;           // 0..1999
    int img = box / MBOX;

    __shared__ int soff[49];
    __shared__ const float* sbase;
    __shared__ int sHW;

    if (threadIdx.x == 0) {
        const float* fmaps[4] = {p2, p3, p4, p5};
        const int   Hs[4] = {200, 100, 50, 25};
        const int   Ws[4] = {304, 152, 76, 38};
        const float sc4[4] = {0.25f, 0.125f, 0.0625f, 0.03125f};

        const float* pr = props + (size_t)box * 4;
        float x1o = pr[0], y1o = pr[1], x2o = pr[2], y2o = pr[3];

        float w = __fsub_rn(x2o, x1o);
        float h = __fsub_rn(y2o, y1o);
        float s = sqrtf(fmaxf(__fmul_rn(w, h), 1e-6f));
        float lv = floorf(__fadd_rn(4.0f, log2f(__fadd_rn(__fdiv_rn(s, 224.0f), 1e-8f))));
        lv = fminf(fmaxf(lv, 2.0f), 5.0f);
        int lvl = (int)lv - 2;      // 0..3

        float sc = sc4[lvl];        // powers of two: multiply is exact
        float x1 = __fmul_rn(x1o, sc), y1 = __fmul_rn(y1o, sc);
        float x2 = __fmul_rn(x2o, sc), y2 = __fmul_rn(y2o, sc);
        float bw = __fdiv_rn(fmaxf(__fsub_rn(x2, x1), 1.0f), 7.0f);
        float bh = __fdiv_rn(fmaxf(__fsub_rn(y2, y1), 1.0f), 7.0f);
        int Wl = Ws[lvl], Hl = Hs[lvl];
        int six[RR], siy[RR];
        for (int j = 0; j < RR; j++) {
            float cs = (float)j + 0.5f;
            float gx = __fadd_rn(x1, __fmul_rn(cs, bw));
            float gy = __fadd_rn(y1, __fmul_rn(cs, bh));
            six[j] = min(max((int)gx, 0), Wl - 1);
            siy[j] = min(max((int)gy, 0), Wl > 0 ? Hl - 1 : 0);
        }
        for (int p = 0; p < 49; p++)
            soff[p] = siy[p / 7] * Wl + six[p % 7];
        sbase = fmaps[lvl] + (size_t)img * CCH * Hl * Wl;
        sHW = Hl * Wl;
    }
    __syncthreads();

    const float* base = sbase;
    int HW = sHW;
    float* out = g_X + (size_t)box * FCIN;
    // FCIN = 12544 = 256 threads * 49 -> 4-element groups: 3136 groups, 12.25/thread
    for (int gidx = threadIdx.x; gidx < FCIN / 4; gidx += blockDim.x) {
        int e = gidx * 4;
        int c = e / 49;
        int p = e - c * 49;
        float4 v;
        float* vp = (float*)&v;
        const float* bc_ = base + (size_t)c * HW;
        #pragma unroll
        for (int j = 0; j < 4; j++) {
            vp[j] = __ldg(bc_ + soff[p]);
            if (++p == 49) { p = 0; bc_ += HW; }
        }
        *(float4*)(out + e) = v;
    }
}

// ---------------- fp16x3 scaled-split tensor GEMM, chunk-compensated --------
// C = relu(A @ B + bias).  A[M,K] fp32 row-major, B[K,N] fp32 row-major.
// K % 64 == 0, N % 64 == 0.  Per CTA: 128m x 64n, 256 threads, 8 warps.
// Split: hi = fp16(x); lo' = fp16((x - hi) * 2048).  Per k16-step 3 MMAs:
// chh += hiA*hiB; cmix += hiA*lo'B + lo'A*hiB.  Fold every 4 tiles (64 k):
// y = fma(cmix, 2^-11, chh); fast2sum into master s (R8-class numerics).
__device__ __forceinline__ void mma_f16(float* c, const uint32_t* a,
                                        uint32_t b0, uint32_t b1) {
    asm volatile(
        "mma.sync.aligned.m16n8k16.row.col.f32.f16.f16.f32 "
        "{%0,%1,%2,%3},{%4,%5,%6,%7},{%8,%9},{%0,%1,%2,%3};\n"
        : "+f"(c[0]), "+f"(c[1]), "+f"(c[2]), "+f"(c[3])
        : "r"(a[0]), "r"(a[1]), "r"(a[2]), "r"(a[3]), "r"(b0), "r"(b1));
}
__device__ __forceinline__ uint32_t split_pair(float x0, float x1, uint32_t& mix) {
    __half h0 = __float2half_rn(x0), h1 = __float2half_rn(x1);
    float r0 = __fmul_rn(__fsub_rn(x0, __half2float(h0)), 2048.0f);
    float r1 = __fmul_rn(__fsub_rn(x1, __half2float(h1)), 2048.0f);
    __half2 m2 = __halves2half2(__float2half_rn(r0), __float2half_rn(r1));
    mix = *(uint32_t*)&m2;
    __half2 h2 = __halves2half2(h0, h1);
    return *(uint32_t*)&h2;
}

template<bool RELU>
__global__ void __launch_bounds__(256) tcgemm_kernel(
    const float* __restrict__ A, const float* __restrict__ B,
    const float* __restrict__ bias, float* __restrict__ Cmat,
    int Mrows, int Kdim, int Ndim)
{
    const int BM = 128, BN = 64, BK = 16;
    const int PA = 132;   // A half2-word pitch (128 rows + 4 pad)
    const int PB = 68;    // B half2-word pitch (64 cols + 4 pad)
    __shared__ uint32_t Ah[2][8][PA], Am[2][8][PA];
    __shared__ uint32_t Bh[2][8][PB], Bm[2][8][PB];

    int tid = threadIdx.x;
    int lane = tid & 31, wid = tid >> 5;
    int g = lane >> 2, tig = lane & 3;
    int warp_m = (wid & 3) * 32;     // 4 warps cover 128 m
    int warp_n = (wid >> 2) * 32;    // 2 warps cover 64 n
    int bm = blockIdx.y * BM, bn = blockIdx.x * BN;

    float s[2][4][4], chh[2][4][4], cmix[2][4][4];
    #pragma unroll
    for (int mt = 0; mt < 2; mt++)
        #pragma unroll
        for (int nt = 0; nt < 4; nt++)
            #pragma unroll
            for (int q = 0; q < 4; q++) {
                s[mt][nt][q] = 0.f; chh[mt][nt][q] = 0.f; cmix[mt][nt][q] = 0.f;
            }

    // fill mapping: A 128m x 16k, two float4/thread; B 16k x 64n, two float2/thread
    int am = tid >> 1, ak = (tid & 1) * 8;       // ak = 0 or 8
    int bk2 = tid >> 5, bn2 = (tid & 31) * 2;    // k2 row 0..7, n pair
    int gr = bm + am;
    bool a_ok = (gr < Mrows);
    const float* Aptr = A + (size_t)(a_ok ? gr : 0) * Kdim + ak;
    const float* Bptr0 = B + (size_t)(2 * bk2 + 0) * Ndim + bn + bn2;
    const float* Bptr1 = B + (size_t)(2 * bk2 + 1) * Ndim + bn + bn2;

    float4 av0 = make_float4(0.f,0.f,0.f,0.f), av1 = av0;
    float2 bv0, bv1;
    if (a_ok) { av0 = *(const float4*)(Aptr); av1 = *(const float4*)(Aptr + 4); }
    bv0 = *(const float2*)(Bptr0);
    bv1 = *(const float2*)(Bptr1);

    // store tile 0
    {
        uint32_t m0, m1, m2w, m3;
        Ah[0][ak/2 + 0][am] = split_pair(av0.x, av0.y, m0); Am[0][ak/2 + 0][am] = m0;
        Ah[0][ak/2 + 1][am] = split_pair(av0.z, av0.w, m1); Am[0][ak/2 + 1][am] = m1;
        Ah[0][ak/2 + 2][am] = split_pair(av1.x, av1.y, m2w); Am[0][ak/2 + 2][am] = m2w;
        Ah[0][ak/2 + 3][am] = split_pair(av1.z, av1.w, m3); Am[0][ak/2 + 3][am] = m3;
        uint32_t mb0, mb1;
        Bh[0][bk2][bn2 + 0] = split_pair(bv0.x, bv1.x, mb0); Bm[0][bk2][bn2 + 0] = mb0;
        Bh[0][bk2][bn2 + 1] = split_pair(bv0.y, bv1.y, mb1); Bm[0][bk2][bn2 + 1] = mb1;
    }
    __syncthreads();

    int buf = 0, tile = 0;
    for (int k0 = BK; k0 <= Kdim; k0 += BK) {
        // prefetch next tile into registers
        if (k0 < Kdim) {
            if (a_ok) { av0 = *(const float4*)(Aptr + k0); av1 = *(const float4*)(Aptr + k0 + 4); }
            bv0 = *(const float2*)(Bptr0 + (size_t)k0 * Ndim);
            bv1 = *(const float2*)(Bptr1 + (size_t)k0 * Ndim);
        }

        // ---- A fragments up front; B per nt (proven schedule) ----
        uint32_t aH[2][4], aM[2][4];
        #pragma unroll
        for (int mt = 0; mt < 2; mt++) {
            int r0 = warp_m + mt * 16 + g;
            aH[mt][0] = Ah[buf][tig    ][r0    ];
            aH[mt][1] = Ah[buf][tig    ][r0 + 8];
            aH[mt][2] = Ah[buf][tig + 4][r0    ];
            aH[mt][3] = Ah[buf][tig + 4][r0 + 8];
            aM[mt][0] = Am[buf][tig    ][r0    ];
            aM[mt][1] = Am[buf][tig    ][r0 + 8];
            aM[mt][2] = Am[buf][tig + 4][r0    ];
            aM[mt][3] = Am[buf][tig + 4][r0 + 8];
        }
        #pragma unroll
        for (int nt = 0; nt < 4; nt++) {
            int nn = warp_n + nt * 8 + g;
            uint32_t b0h = Bh[buf][tig    ][nn];
            uint32_t b1h = Bh[buf][tig + 4][nn];
            uint32_t b0m = Bm[buf][tig    ][nn];
            uint32_t b1m = Bm[buf][tig + 4][nn];
            #pragma unroll
            for (int mt = 0; mt < 2; mt++) {
                mma_f16(chh[mt][nt],  aH[mt], b0h, b1h);   // hi*hi
                mma_f16(cmix[mt][nt], aH[mt], b0m, b1m);   // hi*lo'
                mma_f16(cmix[mt][nt], aM[mt], b0h, b1h);   // lo'*hi
            }
        }

        // ---- fold every 4 tiles (64 k): combine scales + fast2sum ----
        tile++;
        if ((tile & 3) == 0) {
            #pragma unroll
            for (int mt = 0; mt < 2; mt++)
                #pragma unroll
                for (int nt = 0; nt < 4; nt++)
                    #pragma unroll
                    for (int q = 0; q < 4; q++) {
                        float y = __fmaf_rn(cmix[mt][nt][q], 4.8828125e-4f, chh[mt][nt][q]);
                        float t = __fadd_rn(s[mt][nt][q], y);
                        chh[mt][nt][q] = __fadd_rn(__fsub_rn(s[mt][nt][q], t), y);
                        cmix[mt][nt][q] = 0.f;
                        s[mt][nt][q] = t;
                    }
        }

        // ---- store prefetched tile into other buffer ----
        if (k0 < Kdim) {
            int nb = buf ^ 1;
            uint32_t m0, m1, m2w, m3;
            Ah[nb][ak/2 + 0][am] = split_pair(av0.x, av0.y, m0); Am[nb][ak/2 + 0][am] = m0;
            Ah[nb][ak/2 + 1][am] = split_pair(av0.z, av0.w, m1); Am[nb][ak/2 + 1][am] = m1;
            Ah[nb][ak/2 + 2][am] = split_pair(av1.x, av1.y, m2w); Am[nb][ak/2 + 2][am] = m2w;
            Ah[nb][ak/2 + 3][am] = split_pair(av1.z, av1.w, m3); Am[nb][ak/2 + 3][am] = m3;
            uint32_t mb0, mb1;
            Bh[nb][bk2][bn2 + 0] = split_pair(bv0.x, bv1.x, mb0); Bm[nb][bk2][bn2 + 0] = mb0;
            Bh[nb][bk2][bn2 + 1] = split_pair(bv0.y, bv1.y, mb1); Bm[nb][bk2][bn2 + 1] = mb1;
            __syncthreads();
            buf = nb;
        }
    }

    // ---- epilogue: rows g / g+8, cols 2*tig, 2*tig+1 (chh holds final comp) --
    #pragma unroll
    for (int mt = 0; mt < 2; mt++) {
        int r0 = bm + warp_m + mt * 16 + g;
        #pragma unroll
        for (int nt = 0; nt < 4; nt++) {
            int col = bn + warp_n + nt * 8 + tig * 2;
            if (r0 < Mrows) {
                float v0 = __fadd_rn(__fadd_rn(s[mt][nt][0], chh[mt][nt][0]), bias[col]);
                float v1 = __fadd_rn(__fadd_rn(s[mt][nt][1], chh[mt][nt][1]), bias[col + 1]);
                if (RELU) { v0 = fmaxf(v0, 0.f); v1 = fmaxf(v1, 0.f); }
                *(float2*)(Cmat + (size_t)r0 * Ndim + col) = make_float2(v0, v1);
            }
            if (r0 + 8 < Mrows) {
                float v2 = __fadd_rn(__fadd_rn(s[mt][nt][2], chh[mt][nt][2]), bias[col]);
                float v3 = __fadd_rn(__fadd_rn(s[mt][nt][3], chh[mt][nt][3]), bias[col + 1]);
                if (RELU) { v2 = fmaxf(v2, 0.f); v3 = fmaxf(v3, 0.f); }
                *(float2*)(Cmat + (size_t)(r0 + 8) * Ndim + col) = make_float2(v2, v3);
            }
        }
    }
}

// ---------------- heads: cls/box projections + softmax + deltas + clip ------
__global__ void heads_kernel(const float* __restrict__ Y2,
                             const float* __restrict__ Wc, const float* __restrict__ bc,
                             const float* __restrict__ Wb, const float* __restrict__ bb,
                             const float* __restrict__ props,
                             const int* __restrict__ isz,
                             float* __restrict__ scores, float* __restrict__ pboxes)
{
    int box = blockIdx.x;
    const float* x = Y2 + (size_t)box * FCD;

    double a0 = 0., a1 = 0., a2 = 0., a3 = 0., a4 = 0., a5 = 0.;
    for (int k = threadIdx.x; k < FCD; k += blockDim.x) {
        double xv = (double)x[k];
        a0 += xv * (double)Wc[k * 2 + 0];
        a1 += xv * (double)Wc[k * 2 + 1];
        a2 += xv * (double)Wb[k * 4 + 0];
        a3 += xv * (double)Wb[k * 4 + 1];
        a4 += xv * (double)Wb[k * 4 + 2];
        a5 += xv * (double)Wb[k * 4 + 3];
    }
    __shared__ double red[6][128];
    red[0][threadIdx.x] = a0; red[1][threadIdx.x] = a1; red[2][threadIdx.x] = a2;
    red[3][threadIdx.x] = a3; red[4][threadIdx.x] = a4; red[5][threadIdx.x] = a5;
    __syncthreads();
    for (int s = 64; s > 0; s >>= 1) {
        if (threadIdx.x < s)
            #pragma unroll
            for (int j = 0; j < 6; j++)
                red[j][threadIdx.x] += red[j][threadIdx.x + s];
        __syncthreads();
    }
    if (threadIdx.x == 0) {
        float l0 = (float)(red[0][0] + (double)bc[0]);
        float l1 = (float)(red[1][0] + (double)bc[1]);
        float m = fmaxf(l0, l1);
        float e0 = expf(__fsub_rn(l0, m)), e1 = expf(__fsub_rn(l1, m));
        scores[box] = __fdiv_rn(e1, __fadd_rn(e0, e1));

        float dx = (float)(red[2][0] + (double)bb[0]);
        float dy = (float)(red[3][0] + (double)bb[1]);
        float dw = fminf((float)(red[4][0] + (double)bb[2]), SCALE_CLAMP);
        float dh = fminf((float)(red[5][0] + (double)bb[3]), SCALE_CLAMP);

        const float* pr = props + (size_t)box * 4;
        float w = __fsub_rn(pr[2], pr[0]), h = __fsub_rn(pr[3], pr[1]);
        float cx = __fadd_rn(pr[0], __fmul_rn(0.5f, w));
        float cy = __fadd_rn(pr[1], __fmul_rn(0.5f, h));
        float pcx = __fadd_rn(__fmul_rn(dx, w), cx);
        float pcy = __fadd_rn(__fmul_rn(dy, h), cy);
        float pw = __fmul_rn(expf(dw), w);
        float ph = __fmul_rn(expf(dh), h);

        int img = box / MBOX;
        float Hh = (float)isz[img * 2 + 0];
        float Ww = (float)isz[img * 2 + 1];
        float bx1 = fminf(fmaxf(__fsub_rn(pcx, __fmul_rn(0.5f, pw)), 0.f), Ww);
        float by1 = fminf(fmaxf(__fsub_rn(pcy, __fmul_rn(0.5f, ph)), 0.f), Hh);
        float bx2 = fminf(fmaxf(__fadd_rn(pcx, __fmul_rn(0.5f, pw)), 0.f), Ww);
        float by2 = fminf(fmaxf(__fadd_rn(pcy, __fmul_rn(0.5f, ph)), 0.f), Hh);
        pboxes[box * 4 + 0] = bx1;
        pboxes[box * 4 + 1] = by1;
        pboxes[box * 4 + 2] = bx2;
        pboxes[box * 4 + 3] = by2;
    }
}

// ---------------- per-image stable sort + NMS + topk + write outputs --------
__global__ void __launch_bounds__(512) sortnms_kernel(
    const float* __restrict__ scores, const float* __restrict__ pboxes,
    float* __restrict__ out)
{
    int img = blockIdx.x;
    int tid = threadIdx.x;

    __shared__ float key[SORT_N];
    __shared__ int   idx[SORT_N];
    __shared__ float4 sb[MBOX];
    __shared__ float  sarea[MBOX];
    __shared__ unsigned long long keepw[NWORDS];

    for (int i = tid; i < SORT_N; i += 512) {
        if (i < MBOX) { key[i] = scores[img * MBOX + i]; idx[i] = i; }
        else          { key[i] = -FLT_MAX;               idx[i] = i; }
    }
    __syncthreads();

    for (int k = 2; k <= SORT_N; k <<= 1) {
        for (int j = k >> 1; j > 0; j >>= 1) {
            for (int i = tid; i < SORT_N; i += 512) {
                int ixj = i ^ j;
                if (ixj > i) {
                    float ka = key[i], kb = key[ixj];
                    int ia = idx[i], ib = idx[ixj];
                    bool a_before_b = (ka > kb) || (ka == kb && ia < ib);
                    bool up = ((i & k) == 0);
                    bool sw = up ? !a_before_b : a_before_b;
                    if (sw) { key[i] = kb; key[ixj] = ka; idx[i] = ib; idx[ixj] = ia; }
                }
            }
            __syncthreads();
        }
    }

    for (int i = tid; i < MBOX; i += 512) {
        const float* p = pboxes + (size_t)(img * MBOX + idx[i]) * 4;
        float4 b = make_float4(p[0], p[1], p[2], p[3]);
        sb[i] = b;
        sarea[i] = (b.z - b.x) * (b.w - b.y);
    }
    __syncthreads();

    unsigned long long* sup = g_sup + (size_t)img * MBOX * NWORDS;
    for (int t = tid; t < MBOX * NWORDS; t += 512) {
        int i = t / NWORDS, w = t % NWORDS;
        float4 a = sb[i];
        float aa = sarea[i];
        unsigned long long m = 0ull;
        int j0 = w * 64;
        int jend = min(j0 + 64, MBOX);
        for (int j = max(j0, i + 1); j < jend; j++) {
            float4 b = sb[j];
            float lx = fmaxf(a.x, b.x), ly = fmaxf(a.y, b.y);
            float rx = fminf(a.z, b.z), ry = fminf(a.w, b.w);
            float iw = fmaxf(rx - lx, 0.f), ih = fmaxf(ry - ly, 0.f);
            float inter = iw * ih;
            float iou = inter / fmaxf(aa + sarea[j] - inter, 1e-9f);
            if (iou > NMS_THRESH) m |= 1ull << (j - j0);
        }
        sup[t] = m;
    }
    if (tid < NWORDS) {
        unsigned long long m = 0ull;
        for (int jj = 0; jj < 64; jj++) {
            int j = tid * 64 + jj;
            if (j < MBOX && key[j] > SCORE_THRESH) m |= 1ull << jj;
        }
        keepw[tid] = m;
    }
    __syncthreads();

    if (tid < 32) {
        volatile unsigned long long* kw = keepw;
        for (int i = 0; i < MBOX; i++) {
            unsigned long long kwi = kw[i >> 6];
            __syncwarp();
            if ((kwi >> (i & 63)) & 1ull) {
                if (tid < NWORDS)
                    kw[tid] = kw[tid] & ~sup[(size_t)i * NWORDS + tid];
            }
            __syncwarp();
        }
        if (tid == 0) {
            int cnt = 0;
            for (int i = 0; i < MBOX; i++) {
                int w = i >> 6, b = i & 63;
                if ((kw[w] >> b) & 1ull) {
                    cnt++;
                    if (cnt > TOPK) kw[w] = kw[w] & ~(1ull << b);
                }
            }
        }
    }
    __syncthreads();

    float* oB = out;
    float* oS = out + (size_t)NIMG * MBOX * 4;
    float* oK = oS + (size_t)NIMG * MBOX;
    float* oO = oK + (size_t)NIMG * MBOX;
    for (int i = tid; i < MBOX; i += 512) {
        float4 b = sb[i];
        size_t o = (size_t)(img * MBOX + i);
        oB[o * 4 + 0] = b.x;
        oB[o * 4 + 1] = b.y;
        oB[o * 4 + 2] = b.z;
        oB[o * 4 + 3] = b.w;
        oS[o] = key[i];
        int w = i >> 6, bb2 = i & 63;
        oK[o] = ((keepw[w] >> bb2) & 1ull) ? 1.0f : 0.0f;
        oO[o] = (float)idx[i];
    }
}

// ---------------- launcher ---------------------------------------------------
extern "C" void kernel_launch(void* const* d_in, const int* in_sizes, int n_in,
                              void* d_out, int out_size)
{
    const float* p2    = (const float*)d_in[0];
    const float* p3    = (const float*)d_in[1];
    const float* p4    = (const float*)d_in[2];
    const float* p5    = (const float*)d_in[3];
    const float* props = (const float*)d_in[4];
    const int*   isz   = (const int*)  d_in[5];
    const float* W1    = (const float*)d_in[6];
    const float* b1    = (const float*)d_in[7];
    const float* W2    = (const float*)d_in[8];
    const float* b2    = (const float*)d_in[9];
    const float* Wc    = (const float*)d_in[10];
    const float* bc    = (const float*)d_in[11];
    const float* Wb    = (const float*)d_in[12];
    const float* bb    = (const float*)d_in[13];
    float* out = (float*)d_out;

    void *pX, *pY1, *pY2, *pSc, *pPb;
    cudaGetSymbolAddress(&pX,  g_X);
    cudaGetSymbolAddress(&pY1, g_Y1);
    cudaGetSymbolAddress(&pY2, g_Y2);
    cudaGetSymbolAddress(&pSc, g_scores);
    cudaGetSymbolAddress(&pPb, g_pboxes);
    float* X  = (float*)pX;
    float* Y1 = (float*)pY1;
    float* Y2 = (float*)pY2;
    float* Sc = (float*)pSc;
    float* Pb = (float*)pPb;

    pool_kernel<<<NBOX, 256>>>(p2, p3, p4, p5, props);

    dim3 g1(FCD / 64, (NBOX + 127) / 128);   // 16 x 16
    tcgemm_kernel<true><<<g1, 256>>>(X, W1, b1, Y1, NBOX, FCIN, FCD);
    tcgemm_kernel<true><<<g1, 256>>>(Y1, W2, b2, Y2, NBOX, FCD, FCD);

    heads_kernel<<<NBOX, 128>>>(Y2, Wc, bc, Wb, bb, props, isz, Sc, Pb);

    sortnms_kernel<<<NIMG, 512>>>(Sc, Pb, out);
}

// round 16
// speedup vs baseline: 1.5022x; 1.2104x over previous
#include <cuda_runtime.h>
#include <cuda_fp16.h>
#include <math.h>
#include <float.h>
#include <stdint.h>

// Problem constants (fixed shapes from reference setup_inputs)
#define NIMG 2
#define MBOX 1000
#define NBOX (NIMG*MBOX)
#define CCH  256
#define RR   7
#define FCIN (CCH*RR*RR)      // 12544
#define FCD  1024
#define SORT_N 1024
#define NWORDS 16             // ceil(1000/64)
#define SCORE_THRESH 0.05f
#define NMS_THRESH 0.5f
#define TOPK 100
#define SCALE_CLAMP 4.135166556742356f  // log(1000/16)

// ---------------- scratch (device globals; no allocations allowed) ----------
__device__ float g_X [NBOX * FCIN];   // pooled features, row-major (2000 x 12544)
__device__ float g_Y1[NBOX * FCD];
__device__ float g_Y2[NBOX * FCD];
__device__ float g_scores[NBOX];
__device__ float g_pboxes[NBOX * 4];  // clipped predicted boxes
__device__ unsigned long long g_sup[NIMG * MBOX * NWORDS];

// ---------------- pooling (ROIAlign-nearest per reference) ------------------
__global__ void pool_kernel(const float* __restrict__ p2, const float* __restrict__ p3,
                            const float* __restrict__ p4, const float* __restrict__ p5,
                            const float* __restrict__ props)
{
    int box = blockIdx.x;           // 0..1999
    int img = box / MBOX;

    __shared__ int soff[49];
    __shared__ const float* sbase;
    __shared__ int sHW;

    if (threadIdx.x == 0) {
        const float* fmaps[4] = {p2, p3, p4, p5};
        const int   Hs[4] = {200, 100, 50, 25};
        const int   Ws[4] = {304, 152, 76, 38};
        const float sc4[4] = {0.25f, 0.125f, 0.0625f, 0.03125f};

        const float* pr = props + (size_t)box * 4;
        float x1o = pr[0], y1o = pr[1], x2o = pr[2], y2o = pr[3];

        float w = __fsub_rn(x2o, x1o);
        float h = __fsub_rn(y2o, y1o);
        float s = sqrtf(fmaxf(__fmul_rn(w, h), 1e-6f));
        float lv = floorf(__fadd_rn(4.0f, log2f(__fadd_rn(__fdiv_rn(s, 224.0f), 1e-8f))));
        lv = fminf(fmaxf(lv, 2.0f), 5.0f);
        int lvl = (int)lv - 2;      // 0..3

        float sc = sc4[lvl];        // powers of two: multiply is exact
        float x1 = __fmul_rn(x1o, sc), y1 = __fmul_rn(y1o, sc);
        float x2 = __fmul_rn(x2o, sc), y2 = __fmul_rn(y2o, sc);
        float bw = __fdiv_rn(fmaxf(__fsub_rn(x2, x1), 1.0f), 7.0f);
        float bh = __fdiv_rn(fmaxf(__fsub_rn(y2, y1), 1.0f), 7.0f);
        int Wl = Ws[lvl], Hl = Hs[lvl];
        int six[RR], siy[RR];
        for (int j = 0; j < RR; j++) {
            float cs = (float)j + 0.5f;
            float gx = __fadd_rn(x1, __fmul_rn(cs, bw));
            float gy = __fadd_rn(y1, __fmul_rn(cs, bh));
            six[j] = min(max((int)gx, 0), Wl - 1);
            siy[j] = min(max((int)gy, 0), Hl - 1);
        }
        for (int p = 0; p < 49; p++)
            soff[p] = siy[p / 7] * Wl + six[p % 7];
        sbase = fmaps[lvl] + (size_t)img * CCH * Hl * Wl;
        sHW = Hl * Wl;
    }
    __syncthreads();

    const float* base = sbase;
    int HW = sHW;
    float* out = g_X + (size_t)box * FCIN;
    for (int gidx = threadIdx.x; gidx < FCIN / 4; gidx += blockDim.x) {
        int e = gidx * 4;
        int c = e / 49;
        int p = e - c * 49;
        float4 v;
        float* vp = (float*)&v;
        const float* bc_ = base + (size_t)c * HW;
        #pragma unroll
        for (int j = 0; j < 4; j++) {
            vp[j] = __ldg(bc_ + soff[p]);
            if (++p == 49) { p = 0; bc_ += HW; }
        }
        *(float4*)(out + e) = v;
    }
}

// ---------------- fp16x3 scaled-split tensor GEMM, chunk-compensated --------
// C = relu(A @ B + bias).  A[M,K] fp32 row-major, B[K,N] fp32 row-major.
// K % 64 == 0, N % 64 == 0.  Per CTA: 128m x 64n, 256 threads, 8 warps.
// __launch_bounds__(256, 2): force 2 CTAs/SM (4 warps/SMSP) so one CTA's
// barrier/LDS/mma stalls are filled by the other (measured 40% stall slack
// at 1 CTA/SM). Numerics identical to R13/R15 (rel_err 5.41e-8).
// Split: hi = fp16(x); lo' = fp16((x - hi) * 2048).  Per k16-step 3 MMAs:
// chh += hiA*hiB; cmix += hiA*lo'B + lo'A*hiB.  Fold every 4 tiles (64 k):
// y = fma(cmix, 2^-11, chh); fast2sum into master s (R8-class numerics).
__device__ __forceinline__ void mma_f16(float* c, const uint32_t* a,
                                        uint32_t b0, uint32_t b1) {
    asm volatile(
        "mma.sync.aligned.m16n8k16.row.col.f32.f16.f16.f32 "
        "{%0,%1,%2,%3},{%4,%5,%6,%7},{%8,%9},{%0,%1,%2,%3};\n"
        : "+f"(c[0]), "+f"(c[1]), "+f"(c[2]), "+f"(c[3])
        : "r"(a[0]), "r"(a[1]), "r"(a[2]), "r"(a[3]), "r"(b0), "r"(b1));
}
__device__ __forceinline__ uint32_t split_pair(float x0, float x1, uint32_t& mix) {
    __half h0 = __float2half_rn(x0), h1 = __float2half_rn(x1);
    float r0 = __fmul_rn(__fsub_rn(x0, __half2float(h0)), 2048.0f);
    float r1 = __fmul_rn(__fsub_rn(x1, __half2float(h1)), 2048.0f);
    __half2 m2 = __halves2half2(__float2half_rn(r0), __float2half_rn(r1));
    mix = *(uint32_t*)&m2;
    __half2 h2 = __halves2half2(h0, h1);
    return *(uint32_t*)&h2;
}

template<bool RELU>
__global__ void __launch_bounds__(256, 2) tcgemm_kernel(
    const float* __restrict__ A, const float* __restrict__ B,
    const float* __restrict__ bias, float* __restrict__ Cmat,
    int Mrows, int Kdim, int Ndim)
{
    const int BM = 128, BN = 64, BK = 16;
    const int PA = 132;   // A half2-word pitch (128 rows + 4 pad)
    const int PB = 68;    // B half2-word pitch (64 cols + 4 pad)
    __shared__ uint32_t Ah[2][8][PA], Am[2][8][PA];
    __shared__ uint32_t Bh[2][8][PB], Bm[2][8][PB];

    int tid = threadIdx.x;
    int lane = tid & 31, wid = tid >> 5;
    int g = lane >> 2, tig = lane & 3;
    int warp_m = (wid & 3) * 32;     // 4 warps cover 128 m
    int warp_n = (wid >> 2) * 32;    // 2 warps cover 64 n
    int bm = blockIdx.y * BM, bn = blockIdx.x * BN;

    float s[2][4][4], chh[2][4][4], cmix[2][4][4];
    #pragma unroll
    for (int mt = 0; mt < 2; mt++)
        #pragma unroll
        for (int nt = 0; nt < 4; nt++)
            #pragma unroll
            for (int q = 0; q < 4; q++) {
                s[mt][nt][q] = 0.f; chh[mt][nt][q] = 0.f; cmix[mt][nt][q] = 0.f;
            }

    // fill mapping: A 128m x 16k, two float4/thread; B 16k x 64n, two float2/thread
    int am = tid >> 1, ak = (tid & 1) * 8;       // ak = 0 or 8
    int bk2 = tid >> 5, bn2 = (tid & 31) * 2;    // k2 row 0..7, n pair
    int gr = bm + am;
    bool a_ok = (gr < Mrows);
    const float* Aptr = A + (size_t)(a_ok ? gr : 0) * Kdim + ak;
    const float* Bptr0 = B + (size_t)(2 * bk2 + 0) * Ndim + bn + bn2;
    const float* Bptr1 = B + (size_t)(2 * bk2 + 1) * Ndim + bn + bn2;

    float4 av0 = make_float4(0.f,0.f,0.f,0.f), av1 = av0;
    float2 bv0, bv1;
    if (a_ok) { av0 = *(const float4*)(Aptr); av1 = *(const float4*)(Aptr + 4); }
    bv0 = *(const float2*)(Bptr0);
    bv1 = *(const float2*)(Bptr1);

    // store tile 0
    {
        uint32_t m0, m1, m2w, m3;
        Ah[0][ak/2 + 0][am] = split_pair(av0.x, av0.y, m0); Am[0][ak/2 + 0][am] = m0;
        Ah[0][ak/2 + 1][am] = split_pair(av0.z, av0.w, m1); Am[0][ak/2 + 1][am] = m1;
        Ah[0][ak/2 + 2][am] = split_pair(av1.x, av1.y, m2w); Am[0][ak/2 + 2][am] = m2w;
        Ah[0][ak/2 + 3][am] = split_pair(av1.z, av1.w, m3); Am[0][ak/2 + 3][am] = m3;
        uint32_t mb0, mb1;
        Bh[0][bk2][bn2 + 0] = split_pair(bv0.x, bv1.x, mb0); Bm[0][bk2][bn2 + 0] = mb0;
        Bh[0][bk2][bn2 + 1] = split_pair(bv0.y, bv1.y, mb1); Bm[0][bk2][bn2 + 1] = mb1;
    }
    __syncthreads();

    int buf = 0, tile = 0;
    for (int k0 = BK; k0 <= Kdim; k0 += BK) {
        // prefetch next tile into registers
        if (k0 < Kdim) {
            if (a_ok) { av0 = *(const float4*)(Aptr + k0); av1 = *(const float4*)(Aptr + k0 + 4); }
            bv0 = *(const float2*)(Bptr0 + (size_t)k0 * Ndim);
            bv1 = *(const float2*)(Bptr1 + (size_t)k0 * Ndim);
        }

        // ---- A fragments up front; B per nt (proven schedule) ----
        uint32_t aH[2][4], aM[2][4];
        #pragma unroll
        for (int mt = 0; mt < 2; mt++) {
            int r0 = warp_m + mt * 16 + g;
            aH[mt][0] = Ah[buf][tig    ][r0    ];
            aH[mt][1] = Ah[buf][tig    ][r0 + 8];
            aH[mt][2] = Ah[buf][tig + 4][r0    ];
            aH[mt][3] = Ah[buf][tig + 4][r0 + 8];
            aM[mt][0] = Am[buf][tig    ][r0    ];
            aM[mt][1] = Am[buf][tig    ][r0 + 8];
            aM[mt][2] = Am[buf][tig + 4][r0    ];
            aM[mt][3] = Am[buf][tig + 4][r0 + 8];
        }
        #pragma unroll
        for (int nt = 0; nt < 4; nt++) {
            int nn = warp_n + nt * 8 + g;
            uint32_t b0h = Bh[buf][tig    ][nn];
            uint32_t b1h = Bh[buf][tig + 4][nn];
            uint32_t b0m = Bm[buf][tig    ][nn];
            uint32_t b1m = Bm[buf][tig + 4][nn];
            #pragma unroll
            for (int mt = 0; mt < 2; mt++) {
                mma_f16(chh[mt][nt],  aH[mt], b0h, b1h);   // hi*hi
                mma_f16(cmix[mt][nt], aH[mt], b0m, b1m);   // hi*lo'
                mma_f16(cmix[mt][nt], aM[mt], b0h, b1h);   // lo'*hi
            }
        }

        // ---- fold every 4 tiles (64 k): combine scales + fast2sum ----
        tile++;
        if ((tile & 3) == 0) {
            #pragma unroll
            for (int mt = 0; mt < 2; mt++)
                #pragma unroll
                for (int nt = 0; nt < 4; nt++)
                    #pragma unroll
                    for (int q = 0; q < 4; q++) {
                        float y = __fmaf_rn(cmix[mt][nt][q], 4.8828125e-4f, chh[mt][nt][q]);
                        float t = __fadd_rn(s[mt][nt][q], y);
                        chh[mt][nt][q] = __fadd_rn(__fsub_rn(s[mt][nt][q], t), y);
                        cmix[mt][nt][q] = 0.f;
                        s[mt][nt][q] = t;
                    }
        }

        // ---- store prefetched tile into other buffer ----
        if (k0 < Kdim) {
            int nb = buf ^ 1;
            uint32_t m0, m1, m2w, m3;
            Ah[nb][ak/2 + 0][am] = split_pair(av0.x, av0.y, m0); Am[nb][ak/2 + 0][am] = m0;
            Ah[nb][ak/2 + 1][am] = split_pair(av0.z, av0.w, m1); Am[nb][ak/2 + 1][am] = m1;
            Ah[nb][ak/2 + 2][am] = split_pair(av1.x, av1.y, m2w); Am[nb][ak/2 + 2][am] = m2w;
            Ah[nb][ak/2 + 3][am] = split_pair(av1.z, av1.w, m3); Am[nb][ak/2 + 3][am] = m3;
            uint32_t mb0, mb1;
            Bh[nb][bk2][bn2 + 0] = split_pair(bv0.x, bv1.x, mb0); Bm[nb][bk2][bn2 + 0] = mb0;
            Bh[nb][bk2][bn2 + 1] = split_pair(bv0.y, bv1.y, mb1); Bm[nb][bk2][bn2 + 1] = mb1;
            __syncthreads();
            buf = nb;
        }
    }

    // ---- epilogue: rows g / g+8, cols 2*tig, 2*tig+1 (chh holds final comp) --
    #pragma unroll
    for (int mt = 0; mt < 2; mt++) {
        int r0 = bm + warp_m + mt * 16 + g;
        #pragma unroll
        for (int nt = 0; nt < 4; nt++) {
            int col = bn + warp_n + nt * 8 + tig * 2;
            if (r0 < Mrows) {
                float v0 = __fadd_rn(__fadd_rn(s[mt][nt][0], chh[mt][nt][0]), bias[col]);
                float v1 = __fadd_rn(__fadd_rn(s[mt][nt][1], chh[mt][nt][1]), bias[col + 1]);
                if (RELU) { v0 = fmaxf(v0, 0.f); v1 = fmaxf(v1, 0.f); }
                *(float2*)(Cmat + (size_t)r0 * Ndim + col) = make_float2(v0, v1);
            }
            if (r0 + 8 < Mrows) {
                float v2 = __fadd_rn(__fadd_rn(s[mt][nt][2], chh[mt][nt][2]), bias[col]);
                float v3 = __fadd_rn(__fadd_rn(s[mt][nt][3], chh[mt][nt][3]), bias[col + 1]);
                if (RELU) { v2 = fmaxf(v2, 0.f); v3 = fmaxf(v3, 0.f); }
                *(float2*)(Cmat + (size_t)(r0 + 8) * Ndim + col) = make_float2(v2, v3);
            }
        }
    }
}

// ---------------- heads: cls/box projections + softmax + deltas + clip ------
__global__ void heads_kernel(const float* __restrict__ Y2,
                             const float* __restrict__ Wc, const float* __restrict__ bc,
                             const float* __restrict__ Wb, const float* __restrict__ bb,
                             const float* __restrict__ props,
                             const int* __restrict__ isz,
                             float* __restrict__ scores, float* __restrict__ pboxes)
{
    int box = blockIdx.x;
    const float* x = Y2 + (size_t)box * FCD;

    double a0 = 0., a1 = 0., a2 = 0., a3 = 0., a4 = 0., a5 = 0.;
    for (int k = threadIdx.x; k < FCD; k += blockDim.x) {
        double xv = (double)x[k];
        a0 += xv * (double)Wc[k * 2 + 0];
        a1 += xv * (double)Wc[k * 2 + 1];
        a2 += xv * (double)Wb[k * 4 + 0];
        a3 += xv * (double)Wb[k * 4 + 1];
        a4 += xv * (double)Wb[k * 4 + 2];
        a5 += xv * (double)Wb[k * 4 + 3];
    }
    __shared__ double red[6][128];
    red[0][threadIdx.x] = a0; red[1][threadIdx.x] = a1; red[2][threadIdx.x] = a2;
    red[3][threadIdx.x] = a3; red[4][threadIdx.x] = a4; red[5][threadIdx.x] = a5;
    __syncthreads();
    for (int s = 64; s > 0; s >>= 1) {
        if (threadIdx.x < s)
            #pragma unroll
            for (int j = 0; j < 6; j++)
                red[j][threadIdx.x] += red[j][threadIdx.x + s];
        __syncthreads();
    }
    if (threadIdx.x == 0) {
        float l0 = (float)(red[0][0] + (double)bc[0]);
        float l1 = (float)(red[1][0] + (double)bc[1]);
        float m = fmaxf(l0, l1);
        float e0 = expf(__fsub_rn(l0, m)), e1 = expf(__fsub_rn(l1, m));
        scores[box] = __fdiv_rn(e1, __fadd_rn(e0, e1));

        float dx = (float)(red[2][0] + (double)bb[0]);
        float dy = (float)(red[3][0] + (double)bb[1]);
        float dw = fminf((float)(red[4][0] + (double)bb[2]), SCALE_CLAMP);
        float dh = fminf((float)(red[5][0] + (double)bb[3]), SCALE_CLAMP);

        const float* pr = props + (size_t)box * 4;
        float w = __fsub_rn(pr[2], pr[0]), h = __fsub_rn(pr[3], pr[1]);
        float cx = __fadd_rn(pr[0], __fmul_rn(0.5f, w));
        float cy = __fadd_rn(pr[1], __fmul_rn(0.5f, h));
        float pcx = __fadd_rn(__fmul_rn(dx, w), cx);
        float pcy = __fadd_rn(__fmul_rn(dy, h), cy);
        float pw = __fmul_rn(expf(dw), w);
        float ph = __fmul_rn(expf(dh), h);

        int img = box / MBOX;
        float Hh = (float)isz[img * 2 + 0];
        float Ww = (float)isz[img * 2 + 1];
        float bx1 = fminf(fmaxf(__fsub_rn(pcx, __fmul_rn(0.5f, pw)), 0.f), Ww);
        float by1 = fminf(fmaxf(__fsub_rn(pcy, __fmul_rn(0.5f, ph)), 0.f), Hh);
        float bx2 = fminf(fmaxf(__fadd_rn(pcx, __fmul_rn(0.5f, pw)), 0.f), Ww);
        float by2 = fminf(fmaxf(__fadd_rn(pcy, __fmul_rn(0.5f, ph)), 0.f), Hh);
        pboxes[box * 4 + 0] = bx1;
        pboxes[box * 4 + 1] = by1;
        pboxes[box * 4 + 2] = bx2;
        pboxes[box * 4 + 3] = by2;
    }
}

// ---------------- per-image stable sort + NMS + topk + write outputs --------
__global__ void __launch_bounds__(512) sortnms_kernel(
    const float* __restrict__ scores, const float* __restrict__ pboxes,
    float* __restrict__ out)
{
    int img = blockIdx.x;
    int tid = threadIdx.x;

    __shared__ float key[SORT_N];
    __shared__ int   idx[SORT_N];
    __shared__ float4 sb[MBOX];
    __shared__ float  sarea[MBOX];
    __shared__ unsigned long long keepw[NWORDS];

    for (int i = tid; i < SORT_N; i += 512) {
        if (i < MBOX) { key[i] = scores[img * MBOX + i]; idx[i] = i; }
        else          { key[i] = -FLT_MAX;               idx[i] = i; }
    }
    __syncthreads();

    for (int k = 2; k <= SORT_N; k <<= 1) {
        for (int j = k >> 1; j > 0; j >>= 1) {
            for (int i = tid; i < SORT_N; i += 512) {
                int ixj = i ^ j;
                if (ixj > i) {
                    float ka = key[i], kb = key[ixj];
                    int ia = idx[i], ib = idx[ixj];
                    bool a_before_b = (ka > kb) || (ka == kb && ia < ib);
                    bool up = ((i & k) == 0);
                    bool sw = up ? !a_before_b : a_before_b;
                    if (sw) { key[i] = kb; key[ixj] = ka; idx[i] = ib; idx[ixj] = ia; }
                }
            }
            __syncthreads();
        }
    }

    for (int i = tid; i < MBOX; i += 512) {
        const float* p = pboxes + (size_t)(img * MBOX + idx[i]) * 4;
        float4 b = make_float4(p[0], p[1], p[2], p[3]);
        sb[i] = b;
        sarea[i] = (b.z - b.x) * (b.w - b.y);
    }
    __syncthreads();

    unsigned long long* sup = g_sup + (size_t)img * MBOX * NWORDS;
    for (int t = tid; t < MBOX * NWORDS; t += 512) {
        int i = t / NWORDS, w = t % NWORDS;
        float4 a = sb[i];
        float aa = sarea[i];
        unsigned long long m = 0ull;
        int j0 = w * 64;
        int jend = min(j0 + 64, MBOX);
        for (int j = max(j0, i + 1); j < jend; j++) {
            float4 b = sb[j];
            float lx = fmaxf(a.x, b.x), ly = fmaxf(a.y, b.y);
            float rx = fminf(a.z, b.z), ry = fminf(a.w, b.w);
            float iw = fmaxf(rx - lx, 0.f), ih = fmaxf(ry - ly, 0.f);
            float inter = iw * ih;
            float iou = inter / fmaxf(aa + sarea[j] - inter, 1e-9f);
            if (iou > NMS_THRESH) m |= 1ull << (j - j0);
        }
        sup[t] = m;
    }
    if (tid < NWORDS) {
        unsigned long long m = 0ull;
        for (int jj = 0; jj < 64; jj++) {
            int j = tid * 64 + jj;
            if (j < MBOX && key[j] > SCORE_THRESH) m |= 1ull << jj;
        }
        keepw[tid] = m;
    }
    __syncthreads();

    if (tid < 32) {
        volatile unsigned long long* kw = keepw;
        for (int i = 0; i < MBOX; i++) {
            unsigned long long kwi = kw[i >> 6];
            __syncwarp();
            if ((kwi >> (i & 63)) & 1ull) {
                if (tid < NWORDS)
                    kw[tid] = kw[tid] & ~sup[(size_t)i * NWORDS + tid];
            }
            __syncwarp();
        }
        if (tid == 0) {
            int cnt = 0;
            for (int i = 0; i < MBOX; i++) {
                int w = i >> 6, b = i & 63;
                if ((kw[w] >> b) & 1ull) {
                    cnt++;
                    if (cnt > TOPK) kw[w] = kw[w] & ~(1ull << b);
                }
            }
        }
    }
    __syncthreads();

    float* oB = out;
    float* oS = out + (size_t)NIMG * MBOX * 4;
    float* oK = oS + (size_t)NIMG * MBOX;
    float* oO = oK + (size_t)NIMG * MBOX;
    for (int i = tid; i < MBOX; i += 512) {
        float4 b = sb[i];
        size_t o = (size_t)(img * MBOX + i);
        oB[o * 4 + 0] = b.x;
        oB[o * 4 + 1] = b.y;
        oB[o * 4 + 2] = b.z;
        oB[o * 4 + 3] = b.w;
        oS[o] = key[i];
        int w = i >> 6, bb2 = i & 63;
        oK[o] = ((keepw[w] >> bb2) & 1ull) ? 1.0f : 0.0f;
        oO[o] = (float)idx[i];
    }
}

// ---------------- launcher ---------------------------------------------------
extern "C" void kernel_launch(void* const* d_in, const int* in_sizes, int n_in,
                              void* d_out, int out_size)
{
    const float* p2    = (const float*)d_in[0];
    const float* p3    = (const float*)d_in[1];
    const float* p4    = (const float*)d_in[2];
    const float* p5    = (const float*)d_in[3];
    const float* props = (const float*)d_in[4];
    const int*   isz   = (const int*)  d_in[5];
    const float* W1    = (const float*)d_in[6];
    const float* b1    = (const float*)d_in[7];
    const float* W2    = (const float*)d_in[8];
    const float* b2    = (const float*)d_in[9];
    const float* Wc    = (const float*)d_in[10];
    const float* bc    = (const float*)d_in[11];
    const float* Wb    = (const float*)d_in[12];
    const float* bb    = (const float*)d_in[13];
    float* out = (float*)d_out;

    void *pX, *pY1, *pY2, *pSc, *pPb;
    cudaGetSymbolAddress(&pX,  g_X);
    cudaGetSymbolAddress(&pY1, g_Y1);
    cudaGetSymbolAddress(&pY2, g_Y2);
    cudaGetSymbolAddress(&pSc, g_scores);
    cudaGetSymbolAddress(&pPb, g_pboxes);
    float* X  = (float*)pX;
    float* Y1 = (float*)pY1;
    float* Y2 = (float*)pY2;
    float* Sc = (float*)pSc;
    float* Pb = (float*)pPb;

    pool_kernel<<<NBOX, 256>>>(p2, p3, p4, p5, props);

    dim3 g1(FCD / 64, (NBOX + 127) / 128);   // 16 x 16
    tcgemm_kernel<true><<<g1, 256>>>(X, W1, b1, Y1, NBOX, FCIN, FCD);
    tcgemm_kernel<true><<<g1, 256>>>(Y1, W2, b2, Y2, NBOX, FCD, FCD);

    heads_kernel<<<NBOX, 128>>>(Y2, Wc, bc, Wb, bb, props, isz, Sc, Pb);

    sortnms_kernel<<<NIMG, 512>>>(Sc, Pb, out);
}